// round 1
// baseline (speedup 1.0000x reference)
#include <cuda_runtime.h>

#define THREADS 1024
#define VPT4    8          // float4 per thread: 8*1024 = 8192 >= 8000
#define N_COLS  32000
#define N4      8000       // 32000 / 4, exact
#define N_ITER  50

__device__ __forceinline__ float warp_sum(float v) {
    #pragma unroll
    for (int o = 16; o > 0; o >>= 1) v += __shfl_xor_sync(0xffffffffu, v, o);
    return v;
}
__device__ __forceinline__ float warp_max(float v) {
    #pragma unroll
    for (int o = 16; o > 0; o >>= 1) v = fmaxf(v, __shfl_xor_sync(0xffffffffu, v, o));
    return v;
}
__device__ __forceinline__ float warp_min(float v) {
    #pragma unroll
    for (int o = 16; o > 0; o >>= 1) v = fminf(v, __shfl_xor_sync(0xffffffffu, v, o));
    return v;
}

__global__ void __launch_bounds__(THREADS, 1)
entmax_kernel(const float* __restrict__ x, float* __restrict__ out) {
    __shared__ float s_a[32];
    __shared__ float s_b[32];
    __shared__ float s_bcast0;
    __shared__ float s_bcast1;

    const int row = blockIdx.x;
    const int tid = threadIdx.x;
    const int wid = tid >> 5;
    const int lid = tid & 31;

    const float4* __restrict__ xrow =
        reinterpret_cast<const float4*>(x + (size_t)row * N_COLS);
    float4* __restrict__ orow =
        reinterpret_cast<float4*>(out + (size_t)row * N_COLS);

    const float NEG_BIG = -1e30f;
    float4 v[VPT4];

    // ---- load row (coalesced float4), track local min/max over valid elems ----
    float lmax = __int_as_float(0xff800000);  // -inf
    float lmin = __int_as_float(0x7f800000);  // +inf
    #pragma unroll
    for (int i = 0; i < VPT4; i++) {
        const int idx = i * THREADS + tid;
        if (idx < N4) {
            v[i] = xrow[idx];
            lmax = fmaxf(lmax, fmaxf(fmaxf(v[i].x, v[i].y), fmaxf(v[i].z, v[i].w)));
            lmin = fminf(lmin, fminf(fminf(v[i].x, v[i].y), fminf(v[i].z, v[i].w)));
        } else {
            v[i] = make_float4(NEG_BIG, NEG_BIG, NEG_BIG, NEG_BIG);
        }
    }

    // ---- block reduce max & min (fused, one barrier pass) ----
    lmax = warp_max(lmax);
    lmin = warp_min(lmin);
    if (lid == 0) { s_a[wid] = lmax; s_b[wid] = lmin; }
    __syncthreads();
    if (wid == 0) {
        float m = s_a[lid];
        float n = s_b[lid];
        m = warp_max(m);
        n = warp_min(n);
        if (lid == 0) { s_bcast0 = m; s_bcast1 = n; }
    }
    __syncthreads();
    const float maxv = s_bcast0;
    const float minv = s_bcast1;

    // ---- z = (alpha-1) * (x - max) = 0.5*(x - max); invalid lanes -> -1e30 ----
    #pragma unroll
    for (int i = 0; i < VPT4; i++) {
        const int idx = i * THREADS + tid;
        if (idx < N4) {
            v[i].x = 0.5f * (v[i].x - maxv);
            v[i].y = 0.5f * (v[i].y - maxv);
            v[i].z = 0.5f * (v[i].z - maxv);
            v[i].w = 0.5f * (v[i].w - maxv);
        }
        // else already NEG_BIG -> clip gives 0 for any tau in range
    }

    // bisection bounds on x_shifted scale (as in reference)
    float tmin = (minv - maxv) - 1.0f;
    float tmax = 0.0f;

    // ---- 50 bisection iterations, row resident in registers ----
    for (int it = 0; it < N_ITER; it++) {
        const float tau = 0.5f * (tmin + tmax);
        float s = 0.0f;
        #pragma unroll
        for (int i = 0; i < VPT4; i++) {
            float d;
            d = fmaxf(v[i].x - tau, 0.0f); s = fmaf(d, d, s);
            d = fmaxf(v[i].y - tau, 0.0f); s = fmaf(d, d, s);
            d = fmaxf(v[i].z - tau, 0.0f); s = fmaf(d, d, s);
            d = fmaxf(v[i].w - tau, 0.0f); s = fmaf(d, d, s);
        }
        // block reduce sum
        s = warp_sum(s);
        if (lid == 0) s_a[wid] = s;
        __syncthreads();
        if (wid == 0) {
            float t = s_a[lid];
            t = warp_sum(t);
            if (lid == 0) s_bcast0 = t;
        }
        __syncthreads();
        const float constraint = s_bcast0 - 1.0f;
        if (constraint < 0.0f) tmin = tau;
        if (constraint > 0.0f) tmax = tau;
    }

    // ---- final y and normalization ----
    const float tau = 0.5f * (tmin + tmax);
    float s = 0.0f;
    #pragma unroll
    for (int i = 0; i < VPT4; i++) {
        float d;
        d = fmaxf(v[i].x - tau, 0.0f); v[i].x = d * d; s = fmaf(d, d, s);
        d = fmaxf(v[i].y - tau, 0.0f); v[i].y = d * d; s = fmaf(d, d, s);
        d = fmaxf(v[i].z - tau, 0.0f); v[i].z = d * d; s = fmaf(d, d, s);
        d = fmaxf(v[i].w - tau, 0.0f); v[i].w = d * d; s = fmaf(d, d, s);
    }
    s = warp_sum(s);
    if (lid == 0) s_a[wid] = s;
    __syncthreads();
    if (wid == 0) {
        float t = s_a[lid];
        t = warp_sum(t);
        if (lid == 0) s_bcast0 = t;
    }
    __syncthreads();
    const float inv = 1.0f / (s_bcast0 + 1e-12f);

    #pragma unroll
    for (int i = 0; i < VPT4; i++) {
        const int idx = i * THREADS + tid;
        if (idx < N4) {
            float4 o;
            o.x = v[i].x * inv;
            o.y = v[i].y * inv;
            o.z = v[i].z * inv;
            o.w = v[i].w * inv;
            orow[idx] = o;
        }
    }
}

extern "C" void kernel_launch(void* const* d_in, const int* in_sizes, int n_in,
                              void* d_out, int out_size) {
    const float* x = (const float*)d_in[0];
    float* out = (float*)d_out;
    const int rows = in_sizes[0] / N_COLS;  // 4096
    entmax_kernel<<<rows, THREADS>>>(x, out);
}

// round 3
// speedup vs baseline: 5.8931x; 5.8931x over previous
#include <cuda_runtime.h>

#define THREADS 1024
#define VPT4    8          // float4 per thread: 8*1024 = 8192 >= 8000
#define N_COLS  32000
#define N4      8000       // 32000 / 4, exact
#define N_ITER  50

__device__ __forceinline__ float warp_sum(float v) {
    #pragma unroll
    for (int o = 16; o > 0; o >>= 1) v += __shfl_xor_sync(0xffffffffu, v, o);
    return v;
}
__device__ __forceinline__ float warp_max(float v) {
    #pragma unroll
    for (int o = 16; o > 0; o >>= 1) v = fmaxf(v, __shfl_xor_sync(0xffffffffu, v, o));
    return v;
}
__device__ __forceinline__ float warp_min(float v) {
    #pragma unroll
    for (int o = 16; o > 0; o >>= 1) v = fminf(v, __shfl_xor_sync(0xffffffffu, v, o));
    return v;
}

__global__ void __launch_bounds__(THREADS, 1)
entmax_kernel(const float* __restrict__ x, float* __restrict__ out) {
    __shared__ float s_a[32];
    __shared__ float s_b[32];
    __shared__ float s_bcast0;
    __shared__ float s_bcast1;

    const int row = blockIdx.x;
    const int tid = threadIdx.x;
    const int wid = tid >> 5;
    const int lid = tid & 31;

    const float4* __restrict__ xrow =
        reinterpret_cast<const float4*>(x + (size_t)row * N_COLS);
    float4* __restrict__ orow =
        reinterpret_cast<float4*>(out + (size_t)row * N_COLS);

    const float NEG_BIG = -1e30f;
    float4 v[VPT4];

    // ---- load row (coalesced float4), track local min/max ----
    float lmax = __int_as_float(0xff800000);  // -inf
    float lmin = __int_as_float(0x7f800000);  // +inf
    #pragma unroll
    for (int i = 0; i < VPT4; i++) {
        const int idx = i * THREADS + tid;
        if (idx < N4) {
            v[i] = xrow[idx];
            lmax = fmaxf(lmax, fmaxf(fmaxf(v[i].x, v[i].y), fmaxf(v[i].z, v[i].w)));
            lmin = fminf(lmin, fminf(fminf(v[i].x, v[i].y), fminf(v[i].z, v[i].w)));
        } else {
            v[i] = make_float4(NEG_BIG, NEG_BIG, NEG_BIG, NEG_BIG);
        }
    }

    // ---- fused block reduce (max & min) ----
    lmax = warp_max(lmax);
    lmin = warp_min(lmin);
    if (lid == 0) { s_a[wid] = lmax; s_b[wid] = lmin; }
    __syncthreads();
    if (wid == 0) {
        float m = s_a[lid];
        float n = s_b[lid];
        m = warp_max(m);
        n = warp_min(n);
        if (lid == 0) { s_bcast0 = m; s_bcast1 = n; }
    }
    __syncthreads();
    const float maxv = s_bcast0;
    const float minv = s_bcast1;

    // ---- z = 0.5 * (x - max); padding lanes stay ~-1e30 (clip -> 0) ----
    #pragma unroll
    for (int i = 0; i < VPT4; i++) {
        const int idx = i * THREADS + tid;
        if (idx < N4) {
            v[i].x = 0.5f * (v[i].x - maxv);
            v[i].y = 0.5f * (v[i].y - maxv);
            v[i].z = 0.5f * (v[i].z - maxv);
            v[i].w = 0.5f * (v[i].w - maxv);
        }
    }

    // ---- scalar fp32 replica of the reference recurrence, assuming
    //      constraint > 0 at every iterate (tmax <- tau, tmin fixed).
    //      Valid iff constraint(tau_1) > 0; tau_1 is the largest iterate
    //      and the constraint fn is decreasing in tau. ----
    const float m_shift = minv - maxv;           // min(x_shifted), fp32
    const float tmin0 = m_shift - 1.0f;
    const float tau1 = 0.5f * (tmin0 + 0.0f);
    float tmaxr = 0.0f;
    #pragma unroll
    for (int it = 0; it < N_ITER; it++) {
        tmaxr = 0.5f * (tmin0 + tmaxr);          // tau = mid; tmax = tau
    }
    const float tau_fast = 0.5f * (tmin0 + tmaxr);

    // ---- one register pass: guard sum at tau1, final sum at tau_fast ----
    float s1 = 0.0f;   // sum clip(z - tau1)^2
    float sf = 0.0f;   // sum clip(z - tau_fast)^2
    #pragma unroll
    for (int i = 0; i < VPT4; i++) {
        float d;
        d = fmaxf(v[i].x - tau1, 0.0f);     s1 = fmaf(d, d, s1);
        d = fmaxf(v[i].y - tau1, 0.0f);     s1 = fmaf(d, d, s1);
        d = fmaxf(v[i].z - tau1, 0.0f);     s1 = fmaf(d, d, s1);
        d = fmaxf(v[i].w - tau1, 0.0f);     s1 = fmaf(d, d, s1);
        d = fmaxf(v[i].x - tau_fast, 0.0f); sf = fmaf(d, d, sf);
        d = fmaxf(v[i].y - tau_fast, 0.0f); sf = fmaf(d, d, sf);
        d = fmaxf(v[i].z - tau_fast, 0.0f); sf = fmaf(d, d, sf);
        d = fmaxf(v[i].w - tau_fast, 0.0f); sf = fmaf(d, d, sf);
    }
    s1 = warp_sum(s1);
    sf = warp_sum(sf);
    if (lid == 0) { s_a[wid] = s1; s_b[wid] = sf; }
    __syncthreads();
    if (wid == 0) {
        float a = s_a[lid];
        float b = s_b[lid];
        a = warp_sum(a);
        b = warp_sum(b);
        if (lid == 0) { s_bcast0 = a; s_bcast1 = b; }
    }
    __syncthreads();
    const float guard = s_bcast0;
    float total = s_bcast1;
    float tau = tau_fast;

    if (guard <= 1.001f) {
        // ---- fallback: exact reference-semantics bisection over registers.
        //      (Never taken for this data; guards pathological inputs.) ----
        float tmin = tmin0, tmax = 0.0f;
        for (int it = 0; it < N_ITER; it++) {
            const float t = 0.5f * (tmin + tmax);
            float s = 0.0f;
            #pragma unroll
            for (int i = 0; i < VPT4; i++) {
                float d;
                d = fmaxf(v[i].x - t, 0.0f); s = fmaf(d, d, s);
                d = fmaxf(v[i].y - t, 0.0f); s = fmaf(d, d, s);
                d = fmaxf(v[i].z - t, 0.0f); s = fmaf(d, d, s);
                d = fmaxf(v[i].w - t, 0.0f); s = fmaf(d, d, s);
            }
            s = warp_sum(s);
            if (lid == 0) s_a[wid] = s;
            __syncthreads();
            if (wid == 0) {
                float u = s_a[lid];
                u = warp_sum(u);
                if (lid == 0) s_bcast0 = u;
            }
            __syncthreads();
            const float constraint = s_bcast0 - 1.0f;
            if (constraint < 0.0f) tmin = t;
            if (constraint > 0.0f) tmax = t;
        }
        tau = 0.5f * (tmin + tmax);
        float s = 0.0f;
        #pragma unroll
        for (int i = 0; i < VPT4; i++) {
            float d;
            d = fmaxf(v[i].x - tau, 0.0f); s = fmaf(d, d, s);
            d = fmaxf(v[i].y - tau, 0.0f); s = fmaf(d, d, s);
            d = fmaxf(v[i].z - tau, 0.0f); s = fmaf(d, d, s);
            d = fmaxf(v[i].w - tau, 0.0f); s = fmaf(d, d, s);
        }
        s = warp_sum(s);
        if (lid == 0) s_a[wid] = s;
        __syncthreads();
        if (wid == 0) {
            float u = s_a[lid];
            u = warp_sum(u);
            if (lid == 0) s_bcast0 = u;
        }
        __syncthreads();
        total = s_bcast0;
    }

    const float inv = 1.0f / (total + 1e-12f);

    // ---- write y = clip(z - tau)^2 * inv ----
    #pragma unroll
    for (int i = 0; i < VPT4; i++) {
        const int idx = i * THREADS + tid;
        if (idx < N4) {
            float4 o;
            float d;
            d = fmaxf(v[i].x - tau, 0.0f); o.x = d * d * inv;
            d = fmaxf(v[i].y - tau, 0.0f); o.y = d * d * inv;
            d = fmaxf(v[i].z - tau, 0.0f); o.z = d * d * inv;
            d = fmaxf(v[i].w - tau, 0.0f); o.w = d * d * inv;
            orow[idx] = o;
        }
    }
}

extern "C" void kernel_launch(void* const* d_in, const int* in_sizes, int n_in,
                              void* d_out, int out_size) {
    const float* x = (const float*)d_in[0];
    float* out = (float*)d_out;
    const int rows = in_sizes[0] / N_COLS;   // 4096
    entmax_kernel<<<rows, THREADS>>>(x, out);
}